// round 2
// baseline (speedup 1.0000x reference)
#include <cuda_runtime.h>

#define FD 128          // feature dim (in == out == 128)
#define NMAX 100000
#define EMAX 1600000

// ---------------- scratch (static device globals; no allocation allowed) ----
__device__ float g_h[(size_t)NMAX * FD];   // x @ W
__device__ float g_dinv[NMAX];             // deg, then rsqrt(deg)
__device__ int   g_count[NMAX];            // histogram / placement cursor
__device__ int   g_rowptr[NMAX + 1];
__device__ int   g_bsum[256];              // block sums for scan (<=98 used)
__device__ int   g_srcs[EMAX];             // CSR: src per edge (sorted by dst)
__device__ float g_norms[EMAX];            // CSR: norm per edge

// ---------------- init: deg = 1 (self-loop weight), count = 0 --------------
__global__ void k_init(int n) {
    int i = blockIdx.x * blockDim.x + threadIdx.x;
    if (i < n) { g_dinv[i] = 1.0f; g_count[i] = 0; }
}

// ---------------- pass 1 over edges: degree + histogram ---------------------
__global__ void k_deg(const int* __restrict__ src, const int* __restrict__ dst,
                      const float* __restrict__ w, int e) {
    int i = blockIdx.x * blockDim.x + threadIdx.x;
    if (i < e) {
        int d = dst[i];
        atomicAdd(&g_dinv[d], w[i]);
        atomicAdd(&g_count[d], 1);
    }
}

// ---------------- dinv = rsqrt(deg) (deg >= 1 always, self-loop) -----------
__global__ void k_rsqrt(int n) {
    int i = blockIdx.x * blockDim.x + threadIdx.x;
    if (i < n) g_dinv[i] = rsqrtf(g_dinv[i]);
}

// ---------------- scan step A: per-block (1024 nodes) sums ------------------
__global__ void k_scanA(int n) {
    __shared__ int s[32];
    int i = blockIdx.x * 1024 + threadIdx.x;
    int c = (i < n) ? g_count[i] : 0;
    int v = c;
    #pragma unroll
    for (int o = 16; o > 0; o >>= 1) v += __shfl_down_sync(0xFFFFFFFFu, v, o);
    int lane = threadIdx.x & 31, wid = threadIdx.x >> 5;
    if (lane == 0) s[wid] = v;
    __syncthreads();
    if (wid == 0) {
        int v2 = s[lane];
        #pragma unroll
        for (int o = 16; o > 0; o >>= 1) v2 += __shfl_down_sync(0xFFFFFFFFu, v2, o);
        if (lane == 0) g_bsum[blockIdx.x] = v2;
    }
}

// ---------------- scan step B: exclusive scan of block sums (nb <= 256) ----
__global__ void k_scanB(int nb) {
    __shared__ int sh[256];
    int t = threadIdx.x;
    int v = (t < nb) ? g_bsum[t] : 0;
    sh[t] = v;
    __syncthreads();
    for (int o = 1; o < 256; o <<= 1) {
        int u = (t >= o) ? sh[t - o] : 0;
        __syncthreads();
        sh[t] += u;
        __syncthreads();
    }
    if (t < nb) g_bsum[t] = sh[t] - v;   // exclusive
}

// ---------------- scan step C: full exclusive scan -> rowptr; reset counts -
__global__ void k_scanC(int n) {
    __shared__ int ws[32];
    int i = blockIdx.x * 1024 + threadIdx.x;
    int c = (i < n) ? g_count[i] : 0;
    int lane = threadIdx.x & 31, wid = threadIdx.x >> 5;
    int inc = c;
    #pragma unroll
    for (int o = 1; o < 32; o <<= 1) {
        int t = __shfl_up_sync(0xFFFFFFFFu, inc, o);
        if (lane >= o) inc += t;
    }
    if (lane == 31) ws[wid] = inc;
    __syncthreads();
    if (wid == 0) {
        int v = ws[lane];
        #pragma unroll
        for (int o = 1; o < 32; o <<= 1) {
            int t = __shfl_up_sync(0xFFFFFFFFu, v, o);
            if (lane >= o) v += t;
        }
        ws[lane] = v;
    }
    __syncthreads();
    int base = (wid > 0) ? ws[wid - 1] : 0;
    int excl = base + inc - c + g_bsum[blockIdx.x];
    if (i < n) {
        g_rowptr[i] = excl;
        g_count[i] = 0;                     // reuse as placement cursor
        if (i == n - 1) g_rowptr[n] = excl + c;
    }
}

// ---------------- pass 2 over edges: place into CSR + precompute norm ------
__global__ void k_place(const int* __restrict__ src, const int* __restrict__ dst,
                        const float* __restrict__ w, int e) {
    int i = blockIdx.x * blockDim.x + threadIdx.x;
    if (i < e) {
        int s = src[i], d = dst[i];
        int pos = g_rowptr[d] + atomicAdd(&g_count[d], 1);
        g_srcs[pos] = s;
        g_norms[pos] = g_dinv[s] * w[i] * g_dinv[d];
    }
}

// ---------------- GEMM: h = x @ W (N x 128 @ 128 x 128, fp32) --------------
// Block tile 64 rows x 128 cols, 256 threads, register tile 8x4.
__global__ void __launch_bounds__(256) k_gemm(const float* __restrict__ x,
                                              const float* __restrict__ W, int n) {
    __shared__ float Wk[8 * FD];      // 8 K-rows of W
    __shared__ float Xs[64][8];       // 64 rows x 8 K
    int tid = threadIdx.x;
    int row0 = blockIdx.x * 64;
    int tc = tid & 31;                // col group: cols tc*4 .. tc*4+3
    int tr = tid >> 5;                // row group: rows tr*8 .. tr*8+7
    float acc[8][4];
    #pragma unroll
    for (int r = 0; r < 8; r++)
        #pragma unroll
        for (int c = 0; c < 4; c++) acc[r][c] = 0.0f;

    for (int k = 0; k < FD; k += 8) {
        __syncthreads();
        // load 8x128 W tile (L2-resident after first block)
        for (int i = tid; i < 8 * FD; i += 256)
            Wk[i] = W[(size_t)(k + (i >> 7)) * FD + (i & 127)];
        // load 64x8 x tile
        for (int i = tid; i < 64 * 8; i += 256) {
            int r = i >> 3, kk = i & 7;
            int gr = row0 + r;
            Xs[r][kk] = (gr < n) ? x[(size_t)gr * FD + k + kk] : 0.0f;
        }
        __syncthreads();
        #pragma unroll
        for (int kk = 0; kk < 8; kk++) {
            float4 wv = *(const float4*)&Wk[kk * FD + tc * 4];
            #pragma unroll
            for (int r = 0; r < 8; r++) {
                float a = Xs[tr * 8 + r][kk];
                acc[r][0] += a * wv.x;
                acc[r][1] += a * wv.y;
                acc[r][2] += a * wv.z;
                acc[r][3] += a * wv.w;
            }
        }
    }
    #pragma unroll
    for (int r = 0; r < 8; r++) {
        int gr = row0 + tr * 8 + r;
        if (gr < n)
            *(float4*)&g_h[(size_t)gr * FD + tc * 4] =
                make_float4(acc[r][0], acc[r][1], acc[r][2], acc[r][3]);
    }
}

// ---------------- gather: one warp per dst node ----------------------------
__global__ void __launch_bounds__(256) k_gather(const float* __restrict__ b,
                                                float* __restrict__ out, int n) {
    int warp = (blockIdx.x * blockDim.x + threadIdx.x) >> 5;
    int lane = threadIdx.x & 31;
    if (warp >= n) return;
    int beg = g_rowptr[warp], end = g_rowptr[warp + 1];
    float4 acc = make_float4(0.f, 0.f, 0.f, 0.f);
    for (int e = beg; e < end; e++) {
        int s = g_srcs[e];
        float nw = g_norms[e];
        float4 hv = *(const float4*)&g_h[(size_t)s * FD + lane * 4];
        acc.x += hv.x * nw; acc.y += hv.y * nw;
        acc.z += hv.z * nw; acc.w += hv.w * nw;
    }
    // self-loop: norm = dinv[i] * 1 * dinv[i]
    float di = g_dinv[warp];
    float sl = di * di;
    float4 hv = *(const float4*)&g_h[(size_t)warp * FD + lane * 4];
    acc.x += hv.x * sl; acc.y += hv.y * sl;
    acc.z += hv.z * sl; acc.w += hv.w * sl;
    // + bias
    float4 bv = *(const float4*)&b[lane * 4];
    acc.x += bv.x; acc.y += bv.y; acc.z += bv.z; acc.w += bv.w;

    size_t off = (size_t)warp * FD + lane * 4;
    *(float4*)&out[off] = acc;
    float4 rv = make_float4(fmaxf(acc.x, 0.f), fmaxf(acc.y, 0.f),
                            fmaxf(acc.z, 0.f), fmaxf(acc.w, 0.f));
    *(float4*)&out[(size_t)n * FD + off] = rv;
}

// ---------------- launcher -------------------------------------------------
extern "C" void kernel_launch(void* const* d_in, const int* in_sizes, int n_in,
                              void* d_out, int out_size) {
    (void)n_in; (void)out_size;
    const float* x  = (const float*)d_in[0];
    const float* W  = (const float*)d_in[1];
    const float* b  = (const float*)d_in[2];
    // d_in[3] = level (scalar, always 0) — ignored
    const int*   ei = (const int*)d_in[4];
    const float* ew = (const float*)d_in[5];

    int n = in_sizes[0] / FD;
    int e = in_sizes[4] / 2;
    const int* src = ei;
    const int* dst = ei + e;

    k_init  <<<(n + 255) / 256, 256>>>(n);
    k_deg   <<<(e + 255) / 256, 256>>>(src, dst, ew, e);
    k_rsqrt <<<(n + 255) / 256, 256>>>(n);

    int nb = (n + 1023) / 1024;
    k_scanA <<<nb, 1024>>>(n);
    k_scanB <<<1, 256>>>(nb);
    k_scanC <<<nb, 1024>>>(n);

    k_place <<<(e + 255) / 256, 256>>>(src, dst, ew, e);
    k_gemm  <<<(n + 63) / 64, 256>>>(x, W, n);

    k_gather<<<(n * 32 + 255) / 256, 256>>>(b, (float*)d_out, n);
}

// round 3
// speedup vs baseline: 1.5019x; 1.5019x over previous
#include <cuda_runtime.h>
#include <cstdint>

#define FD 128          // feature dim (in == out == 128)
#define NMAX 100000
#define EMAX 1600000

// ---------------- scratch (static device globals; no allocation allowed) ----
__device__ float g_h[(size_t)NMAX * FD];   // x @ W
__device__ float g_dinv[NMAX];             // deg, then rsqrt(deg)
__device__ int   g_count[NMAX];            // histogram / placement cursor
__device__ int   g_rowptr[NMAX + 1];
__device__ int   g_bsum[256];              // block sums for scan (<=98 used)
__device__ int   g_srcs[EMAX];             // CSR: src per edge (sorted by dst)
__device__ float g_norms[EMAX];            // CSR: norm per edge

// ---------------- init: deg = 1 (self-loop weight), count = 0 --------------
__global__ void k_init(int n) {
    int i = blockIdx.x * blockDim.x + threadIdx.x;
    if (i < n) { g_dinv[i] = 1.0f; g_count[i] = 0; }
}

// ---------------- pass 1 over edges: degree + histogram ---------------------
__global__ void k_deg(const int* __restrict__ src, const int* __restrict__ dst,
                      const float* __restrict__ w, int e) {
    int i = blockIdx.x * blockDim.x + threadIdx.x;
    if (i < e) {
        int d = dst[i];
        atomicAdd(&g_dinv[d], w[i]);
        atomicAdd(&g_count[d], 1);
    }
}

// ---------------- dinv = rsqrt(deg) (deg >= 1 always, self-loop) -----------
__global__ void k_rsqrt(int n) {
    int i = blockIdx.x * blockDim.x + threadIdx.x;
    if (i < n) g_dinv[i] = rsqrtf(g_dinv[i]);
}

// ---------------- scan step A: per-block (1024 nodes) sums ------------------
__global__ void k_scanA(int n) {
    __shared__ int s[32];
    int i = blockIdx.x * 1024 + threadIdx.x;
    int c = (i < n) ? g_count[i] : 0;
    int v = c;
    #pragma unroll
    for (int o = 16; o > 0; o >>= 1) v += __shfl_down_sync(0xFFFFFFFFu, v, o);
    int lane = threadIdx.x & 31, wid = threadIdx.x >> 5;
    if (lane == 0) s[wid] = v;
    __syncthreads();
    if (wid == 0) {
        int v2 = s[lane];
        #pragma unroll
        for (int o = 16; o > 0; o >>= 1) v2 += __shfl_down_sync(0xFFFFFFFFu, v2, o);
        if (lane == 0) g_bsum[blockIdx.x] = v2;
    }
}

// ---------------- scan step B: exclusive scan of block sums (nb <= 256) ----
__global__ void k_scanB(int nb) {
    __shared__ int sh[256];
    int t = threadIdx.x;
    int v = (t < nb) ? g_bsum[t] : 0;
    sh[t] = v;
    __syncthreads();
    for (int o = 1; o < 256; o <<= 1) {
        int u = (t >= o) ? sh[t - o] : 0;
        __syncthreads();
        sh[t] += u;
        __syncthreads();
    }
    if (t < nb) g_bsum[t] = sh[t] - v;   // exclusive
}

// ---------------- scan step C: full exclusive scan -> rowptr; reset counts -
__global__ void k_scanC(int n) {
    __shared__ int ws[32];
    int i = blockIdx.x * 1024 + threadIdx.x;
    int c = (i < n) ? g_count[i] : 0;
    int lane = threadIdx.x & 31, wid = threadIdx.x >> 5;
    int inc = c;
    #pragma unroll
    for (int o = 1; o < 32; o <<= 1) {
        int t = __shfl_up_sync(0xFFFFFFFFu, inc, o);
        if (lane >= o) inc += t;
    }
    if (lane == 31) ws[wid] = inc;
    __syncthreads();
    if (wid == 0) {
        int v = ws[lane];
        #pragma unroll
        for (int o = 1; o < 32; o <<= 1) {
            int t = __shfl_up_sync(0xFFFFFFFFu, v, o);
            if (lane >= o) v += t;
        }
        ws[lane] = v;
    }
    __syncthreads();
    int base = (wid > 0) ? ws[wid - 1] : 0;
    int excl = base + inc - c + g_bsum[blockIdx.x];
    if (i < n) {
        g_rowptr[i] = excl;
        g_count[i] = 0;                     // reuse as placement cursor
        if (i == n - 1) g_rowptr[n] = excl + c;
    }
}

// ---------------- pass 2 over edges: place into CSR + precompute norm ------
__global__ void k_place(const int* __restrict__ src, const int* __restrict__ dst,
                        const float* __restrict__ w, int e) {
    int i = blockIdx.x * blockDim.x + threadIdx.x;
    if (i < e) {
        int s = src[i], d = dst[i];
        int pos = g_rowptr[d] + atomicAdd(&g_count[d], 1);
        g_srcs[pos] = s;
        g_norms[pos] = g_dinv[s] * w[i] * g_dinv[d];
    }
}

// ---------------- GEMM: h = x @ W via TF32 mma.sync ------------------------
// Block tile 64x128, 8 warps. Warp tile m16 x n64 (warpM 0..3, warpN 0..1).
// K chunked by 32 through shared memory; strides chosen conflict-free.
__device__ __forceinline__ uint32_t f2tf32(float f) {
    uint32_t r;
    asm("cvt.rna.tf32.f32 %0, %1;" : "=r"(r) : "f"(f));
    return r;
}

#define BM  64
#define KCH 32
#define AST 36    // A smem row stride: (36*r + k) % 32 = (4r + k) % 32, distinct
#define WST 136   // W smem row stride: (136*k + n) % 32 = (8k + n) % 32, distinct

__global__ void __launch_bounds__(256) k_gemm(const float* __restrict__ x,
                                              const float* __restrict__ W, int n) {
    __shared__ uint32_t As[BM * AST];     // 64 x 32 tf32 (padded)
    __shared__ uint32_t Ws[KCH * WST];    // 32 x 128 tf32 (padded)
    int tid = threadIdx.x;
    int lane = tid & 31, wid = tid >> 5;
    int warpM = wid & 3, warpN = wid >> 2;
    int row0 = blockIdx.x * BM;
    int qr = lane >> 2;                   // quad row 0..7
    int qk = lane & 3;                    // quad k   0..3

    float c[8][4];
    #pragma unroll
    for (int t = 0; t < 8; t++)
        #pragma unroll
        for (int j = 0; j < 4; j++) c[t][j] = 0.0f;

    for (int kc = 0; kc < FD; kc += KCH) {
        __syncthreads();
        // stage A (64 x 32): 8 elems/thread, coalesced
        #pragma unroll
        for (int i = tid; i < BM * KCH; i += 256) {
            int r = i >> 5, k = i & 31;
            int gr = row0 + r;
            float v = (gr < n) ? x[(size_t)gr * FD + kc + k] : 0.0f;
            As[r * AST + k] = f2tf32(v);
        }
        // stage W (32 x 128): 16 elems/thread, coalesced
        #pragma unroll
        for (int i = tid; i < KCH * FD; i += 256) {
            int k = i >> 7, nn = i & 127;
            Ws[k * WST + nn] = f2tf32(W[(size_t)(kc + k) * FD + nn]);
        }
        __syncthreads();

        #pragma unroll
        for (int kk = 0; kk < KCH; kk += 8) {
            int ar = warpM * 16 + qr;
            uint32_t a0 = As[ar * AST + kk + qk];
            uint32_t a1 = As[(ar + 8) * AST + kk + qk];
            uint32_t a2 = As[ar * AST + kk + qk + 4];
            uint32_t a3 = As[(ar + 8) * AST + kk + qk + 4];
            #pragma unroll
            for (int t = 0; t < 8; t++) {
                int bn = warpN * 64 + t * 8 + qr;
                uint32_t b0 = Ws[(kk + qk) * WST + bn];
                uint32_t b1 = Ws[(kk + qk + 4) * WST + bn];
                asm volatile(
                    "mma.sync.aligned.m16n8k8.row.col.f32.tf32.tf32.f32 "
                    "{%0,%1,%2,%3}, {%4,%5,%6,%7}, {%8,%9}, {%0,%1,%2,%3};"
                    : "+f"(c[t][0]), "+f"(c[t][1]), "+f"(c[t][2]), "+f"(c[t][3])
                    : "r"(a0), "r"(a1), "r"(a2), "r"(a3), "r"(b0), "r"(b1));
            }
        }
    }

    // store C: c0/c1 at (mr, col..col+1), c2/c3 at (mr+8, col..col+1)
    int mr = row0 + warpM * 16 + qr;
    #pragma unroll
    for (int t = 0; t < 8; t++) {
        int col = warpN * 64 + t * 8 + 2 * qk;
        if (mr < n)
            *(float2*)&g_h[(size_t)mr * FD + col] = make_float2(c[t][0], c[t][1]);
        if (mr + 8 < n)
            *(float2*)&g_h[(size_t)(mr + 8) * FD + col] = make_float2(c[t][2], c[t][3]);
    }
}

// ---------------- gather: one warp per dst node ----------------------------
__global__ void __launch_bounds__(256) k_gather(const float* __restrict__ b,
                                                float* __restrict__ out, int n) {
    int warp = (blockIdx.x * blockDim.x + threadIdx.x) >> 5;
    int lane = threadIdx.x & 31;
    if (warp >= n) return;
    int beg = g_rowptr[warp], end = g_rowptr[warp + 1];
    float4 acc = make_float4(0.f, 0.f, 0.f, 0.f);

    int e = beg;
    if (e < end) {
        int s = g_srcs[e];
        float nw = g_norms[e];
        for (;;) {
            const float4 hv = *(const float4*)&g_h[(size_t)s * FD + lane * 4];
            ++e;
            int sn = 0; float nwn = 0.f;
            bool more = (e < end);
            if (more) { sn = g_srcs[e]; nwn = g_norms[e]; }   // prefetch next index
            acc.x += hv.x * nw; acc.y += hv.y * nw;
            acc.z += hv.z * nw; acc.w += hv.w * nw;
            if (!more) break;
            s = sn; nw = nwn;
        }
    }

    // self-loop: norm = dinv[i]^2, then + bias
    float di = g_dinv[warp];
    float sl = di * di;
    float4 hv = *(const float4*)&g_h[(size_t)warp * FD + lane * 4];
    acc.x += hv.x * sl; acc.y += hv.y * sl;
    acc.z += hv.z * sl; acc.w += hv.w * sl;
    float4 bv = *(const float4*)&b[lane * 4];
    acc.x += bv.x; acc.y += bv.y; acc.z += bv.z; acc.w += bv.w;

    size_t off = (size_t)warp * FD + lane * 4;
    *(float4*)&out[off] = acc;
    float4 rv = make_float4(fmaxf(acc.x, 0.f), fmaxf(acc.y, 0.f),
                            fmaxf(acc.z, 0.f), fmaxf(acc.w, 0.f));
    *(float4*)&out[(size_t)n * FD + off] = rv;
}

// ---------------- launcher -------------------------------------------------
extern "C" void kernel_launch(void* const* d_in, const int* in_sizes, int n_in,
                              void* d_out, int out_size) {
    (void)n_in; (void)out_size;
    const float* x  = (const float*)d_in[0];
    const float* W  = (const float*)d_in[1];
    const float* b  = (const float*)d_in[2];
    // d_in[3] = level (scalar, always 0) — ignored
    const int*   ei = (const int*)d_in[4];
    const float* ew = (const float*)d_in[5];

    int n = in_sizes[0] / FD;
    int e = in_sizes[4] / 2;
    const int* src = ei;
    const int* dst = ei + e;

    k_init  <<<(n + 255) / 256, 256>>>(n);
    k_deg   <<<(e + 255) / 256, 256>>>(src, dst, ew, e);
    k_rsqrt <<<(n + 255) / 256, 256>>>(n);

    int nb = (n + 1023) / 1024;
    k_scanA <<<nb, 1024>>>(n);
    k_scanB <<<1, 256>>>(nb);
    k_scanC <<<nb, 1024>>>(n);

    k_place <<<(e + 255) / 256, 256>>>(src, dst, ew, e);
    k_gemm  <<<(n + BM - 1) / BM, 256>>>(x, W, n);

    k_gather<<<(n * 32 + 255) / 256, 256>>>(b, (float*)d_out, n);
}

// round 5
// speedup vs baseline: 1.6759x; 1.1159x over previous
#include <cuda_runtime.h>
#include <cuda_fp16.h>
#include <cstdint>

#define FD 128          // feature dim (in == out == 128)
#define NMAX 100000
#define EMAX 1600000

// ---------------- scratch (static device globals; no allocation allowed) ----
__device__ __half g_h[(size_t)NMAX * FD];  // x @ W   (fp16 storage, fp32 math)
__device__ float g_dinv[NMAX];             // deg, then rsqrt(deg)
__device__ int   g_count[NMAX];            // histogram / placement cursor
__device__ int   g_rowptr[NMAX + 1];
__device__ int   g_bsum[256];              // block sums for scan (<=98 used)
__device__ int   g_srcs[EMAX];             // CSR: src per edge (sorted by dst)
__device__ float g_norms[EMAX];            // CSR: norm per edge

// ---------------- init: deg = 1 (self-loop weight), count = 0 --------------
__global__ void k_init(int n) {
    int i = blockIdx.x * blockDim.x + threadIdx.x;
    if (i < n) { g_dinv[i] = 1.0f; g_count[i] = 0; }
}

// ---------------- pass 1 over edges: degree + histogram ---------------------
__global__ void k_deg(const int* __restrict__ src, const int* __restrict__ dst,
                      const float* __restrict__ w, int e) {
    int i = blockIdx.x * blockDim.x + threadIdx.x;
    if (i < e) {
        int d = dst[i];
        atomicAdd(&g_dinv[d], w[i]);
        atomicAdd(&g_count[d], 1);
    }
}

// ---------------- scan step A: per-block sums; also dinv = rsqrt(deg) ------
__global__ void k_scanA(int n) {
    __shared__ int s[32];
    int i = blockIdx.x * 1024 + threadIdx.x;
    int c = (i < n) ? g_count[i] : 0;
    if (i < n) g_dinv[i] = rsqrtf(g_dinv[i]);   // fused (deg >= 1 always)
    int v = c;
    #pragma unroll
    for (int o = 16; o > 0; o >>= 1) v += __shfl_down_sync(0xFFFFFFFFu, v, o);
    int lane = threadIdx.x & 31, wid = threadIdx.x >> 5;
    if (lane == 0) s[wid] = v;
    __syncthreads();
    if (wid == 0) {
        int v2 = s[lane];
        #pragma unroll
        for (int o = 16; o > 0; o >>= 1) v2 += __shfl_down_sync(0xFFFFFFFFu, v2, o);
        if (lane == 0) g_bsum[blockIdx.x] = v2;
    }
}

// ---------------- scan step B: exclusive scan of block sums (nb <= 256) ----
__global__ void k_scanB(int nb) {
    __shared__ int sh[256];
    int t = threadIdx.x;
    int v = (t < nb) ? g_bsum[t] : 0;
    sh[t] = v;
    __syncthreads();
    for (int o = 1; o < 256; o <<= 1) {
        int u = (t >= o) ? sh[t - o] : 0;
        __syncthreads();
        sh[t] += u;
        __syncthreads();
    }
    if (t < nb) g_bsum[t] = sh[t] - v;   // exclusive
}

// ---------------- scan step C: full exclusive scan -> rowptr; reset counts -
__global__ void k_scanC(int n) {
    __shared__ int ws[32];
    int i = blockIdx.x * 1024 + threadIdx.x;
    int c = (i < n) ? g_count[i] : 0;
    int lane = threadIdx.x & 31, wid = threadIdx.x >> 5;
    int inc = c;
    #pragma unroll
    for (int o = 1; o < 32; o <<= 1) {
        int t = __shfl_up_sync(0xFFFFFFFFu, inc, o);
        if (lane >= o) inc += t;
    }
    if (lane == 31) ws[wid] = inc;
    __syncthreads();
    if (wid == 0) {
        int v = ws[lane];
        #pragma unroll
        for (int o = 1; o < 32; o <<= 1) {
            int t = __shfl_up_sync(0xFFFFFFFFu, v, o);
            if (lane >= o) v += t;
        }
        ws[lane] = v;
    }
    __syncthreads();
    int base = (wid > 0) ? ws[wid - 1] : 0;
    int excl = base + inc - c + g_bsum[blockIdx.x];
    if (i < n) {
        g_rowptr[i] = excl;
        g_count[i] = 0;                     // reuse as placement cursor
        if (i == n - 1) g_rowptr[n] = excl + c;
    }
}

// ---------------- pass 2 over edges: place into CSR + precompute norm ------
__global__ void k_place(const int* __restrict__ src, const int* __restrict__ dst,
                        const float* __restrict__ w, int e) {
    int i = blockIdx.x * blockDim.x + threadIdx.x;
    if (i < e) {
        int s = src[i], d = dst[i];
        int pos = g_rowptr[d] + atomicAdd(&g_count[d], 1);
        g_srcs[pos] = s;
        g_norms[pos] = g_dinv[s] * w[i] * g_dinv[d];
    }
}

// ---------------- GEMM: h = x @ W via TF32 mma.sync, fp16 output -----------
__device__ __forceinline__ uint32_t f2tf32(float f) {
    uint32_t r;
    asm("cvt.rna.tf32.f32 %0, %1;" : "=r"(r) : "f"(f));
    return r;
}

#define BM  64
#define KCH 32
#define AST 36    // A smem row stride: (36*r + k) % 32 distinct
#define WST 136   // W smem row stride: (136*k + n) % 32 distinct

__global__ void __launch_bounds__(256) k_gemm(const float* __restrict__ x,
                                              const float* __restrict__ W, int n) {
    __shared__ uint32_t As[BM * AST];     // 64 x 32 tf32 (padded)
    __shared__ uint32_t Ws[KCH * WST];    // 32 x 128 tf32 (padded)
    int tid = threadIdx.x;
    int lane = tid & 31, wid = tid >> 5;
    int warpM = wid & 3, warpN = wid >> 2;
    int row0 = blockIdx.x * BM;
    int qr = lane >> 2;                   // quad row 0..7
    int qk = lane & 3;                    // quad k   0..3

    float c[8][4];
    #pragma unroll
    for (int t = 0; t < 8; t++)
        #pragma unroll
        for (int j = 0; j < 4; j++) c[t][j] = 0.0f;

    for (int kc = 0; kc < FD; kc += KCH) {
        __syncthreads();
        #pragma unroll
        for (int i = tid; i < BM * KCH; i += 256) {
            int r = i >> 5, k = i & 31;
            int gr = row0 + r;
            float v = (gr < n) ? x[(size_t)gr * FD + kc + k] : 0.0f;
            As[r * AST + k] = f2tf32(v);
        }
        #pragma unroll
        for (int i = tid; i < KCH * FD; i += 256) {
            int k = i >> 7, nn = i & 127;
            Ws[k * WST + nn] = f2tf32(W[(size_t)(kc + k) * FD + nn]);
        }
        __syncthreads();

        #pragma unroll
        for (int kk = 0; kk < KCH; kk += 8) {
            int ar = warpM * 16 + qr;
            uint32_t a0 = As[ar * AST + kk + qk];
            uint32_t a1 = As[(ar + 8) * AST + kk + qk];
            uint32_t a2 = As[ar * AST + kk + qk + 4];
            uint32_t a3 = As[(ar + 8) * AST + kk + qk + 4];
            #pragma unroll
            for (int t = 0; t < 8; t++) {
                int bn = warpN * 64 + t * 8 + qr;
                uint32_t b0 = Ws[(kk + qk) * WST + bn];
                uint32_t b1 = Ws[(kk + qk + 4) * WST + bn];
                asm volatile(
                    "mma.sync.aligned.m16n8k8.row.col.f32.tf32.tf32.f32 "
                    "{%0,%1,%2,%3}, {%4,%5,%6,%7}, {%8,%9}, {%0,%1,%2,%3};"
                    : "+f"(c[t][0]), "+f"(c[t][1]), "+f"(c[t][2]), "+f"(c[t][3])
                    : "r"(a0), "r"(a1), "r"(a2), "r"(a3), "r"(b0), "r"(b1));
            }
        }
    }

    int mr = row0 + warpM * 16 + qr;
    #pragma unroll
    for (int t = 0; t < 8; t++) {
        int col = warpN * 64 + t * 8 + 2 * qk;
        if (mr < n)
            *(__half2*)&g_h[(size_t)mr * FD + col] = __floats2half2_rn(c[t][0], c[t][1]);
        if (mr + 8 < n)
            *(__half2*)&g_h[(size_t)(mr + 8) * FD + col] = __floats2half2_rn(c[t][2], c[t][3]);
    }
}

// ---------------- gather: one warp per dst node (fp16 h rows) --------------
__device__ __forceinline__ void fma_row(float4& acc, uint2 raw, float nw) {
    __half2 h0 = *reinterpret_cast<__half2*>(&raw.x);
    __half2 h1 = *reinterpret_cast<__half2*>(&raw.y);
    float2 f0 = __half22float2(h0), f1 = __half22float2(h1);
    acc.x += f0.x * nw; acc.y += f0.y * nw;
    acc.z += f1.x * nw; acc.w += f1.y * nw;
}

__global__ void __launch_bounds__(256) k_gather(const float* __restrict__ b,
                                                float* __restrict__ out, int n) {
    int warp = (blockIdx.x * blockDim.x + threadIdx.x) >> 5;
    int lane = threadIdx.x & 31;
    if (warp >= n) return;
    int beg = g_rowptr[warp], end = g_rowptr[warp + 1];
    float4 acc = make_float4(0.f, 0.f, 0.f, 0.f);

    int e = beg;
    if (e < end) {
        int s = g_srcs[e];
        float nw = g_norms[e];
        for (;;) {
            uint2 raw = *(const uint2*)&g_h[(size_t)s * FD + lane * 4];
            ++e;
            int sn = 0; float nwn = 0.f;
            bool more = (e < end);
            if (more) { sn = g_srcs[e]; nwn = g_norms[e]; }   // prefetch next index
            fma_row(acc, raw, nw);
            if (!more) break;
            s = sn; nw = nwn;
        }
    }

    // self-loop: norm = dinv[i]^2, then + bias
    float di = g_dinv[warp];
    uint2 raw = *(const uint2*)&g_h[(size_t)warp * FD + lane * 4];
    fma_row(acc, raw, di * di);
    float4 bv = *(const float4*)&b[lane * 4];
    acc.x += bv.x; acc.y += bv.y; acc.z += bv.z; acc.w += bv.w;

    size_t off = (size_t)warp * FD + lane * 4;
    *(float4*)&out[off] = acc;
    float4 rv = make_float4(fmaxf(acc.x, 0.f), fmaxf(acc.y, 0.f),
                            fmaxf(acc.z, 0.f), fmaxf(acc.w, 0.f));
    *(float4*)&out[(size_t)n * FD + off] = rv;
}

// ---------------- launcher -------------------------------------------------
static cudaStream_t g_s2 = nullptr;
static cudaEvent_t  g_evFork = nullptr, g_evJoin = nullptr;

extern "C" void kernel_launch(void* const* d_in, const int* in_sizes, int n_in,
                              void* d_out, int out_size) {
    (void)n_in; (void)out_size;
    const float* x  = (const float*)d_in[0];
    const float* W  = (const float*)d_in[1];
    const float* b  = (const float*)d_in[2];
    // d_in[3] = level (scalar, always 0) — ignored
    const int*   ei = (const int*)d_in[4];
    const float* ew = (const float*)d_in[5];

    int n = in_sizes[0] / FD;
    int e = in_sizes[4] / 2;
    const int* src = ei;
    const int* dst = ei + e;

    if (g_s2 == nullptr) {   // one-time resource setup (first call = correctness run)
        cudaStreamCreateWithFlags(&g_s2, cudaStreamNonBlocking);
        cudaEventCreateWithFlags(&g_evFork, cudaEventDisableTiming);
        cudaEventCreateWithFlags(&g_evJoin, cudaEventDisableTiming);
    }

    // fork: GEMM runs on g_s2 concurrently with the edge/CSR pipeline
    cudaEventRecord(g_evFork, 0);
    cudaStreamWaitEvent(g_s2, g_evFork, 0);
    k_gemm<<<(n + BM - 1) / BM, 256, 0, g_s2>>>(x, W, n);
    cudaEventRecord(g_evJoin, g_s2);

    // edge / CSR pipeline on the default stream
    k_init  <<<(n + 255) / 256, 256>>>(n);
    k_deg   <<<(e + 255) / 256, 256>>>(src, dst, ew, e);

    int nb = (n + 1023) / 1024;
    k_scanA <<<nb, 1024>>>(n);
    k_scanB <<<1, 256>>>(nb);
    k_scanC <<<nb, 1024>>>(n);

    k_place <<<(e + 255) / 256, 256>>>(src, dst, ew, e);

    // join: gather needs both h and the CSR
    cudaStreamWaitEvent(0, g_evJoin, 0);
    k_gather<<<(n * 32 + 255) / 256, 256>>>(b, (float*)d_out, n);
}

// round 6
// speedup vs baseline: 1.9644x; 1.1721x over previous
#include <cuda_runtime.h>
#include <cuda_fp16.h>
#include <cstdint>

#define FD 128          // feature dim (in == out == 128)
#define NMAX 100000
#define EMAX 1600000

// ---------------- scratch (static device globals; no allocation allowed) ----
__device__ __half g_h[(size_t)NMAX * FD];  // x @ W   (fp16 storage, fp32 math)
__device__ float g_dinv[NMAX];             // deg, then rsqrt(deg)
__device__ int   g_count[NMAX];            // histogram / placement cursor
__device__ int   g_rowptr[NMAX + 1];
__device__ int   g_bsum[256];              // block sums for scan (<=98 used)
__device__ uint2 g_edge[EMAX];             // CSR: packed (src, norm) per edge

// ---------------- init: deg = 1 (self-loop weight), count = 0 --------------
__global__ void k_init(int n) {
    int i = blockIdx.x * blockDim.x + threadIdx.x;
    if (i < n) { g_dinv[i] = 1.0f; g_count[i] = 0; }
}

// ---------------- pass 1 over edges: degree + histogram ---------------------
__global__ void k_deg(const int* __restrict__ src, const int* __restrict__ dst,
                      const float* __restrict__ w, int e) {
    int i = blockIdx.x * blockDim.x + threadIdx.x;
    if (i < e) {
        int d = dst[i];
        atomicAdd(&g_dinv[d], w[i]);
        atomicAdd(&g_count[d], 1);
    }
}

// ---------------- scan step A: per-block sums; also dinv = rsqrt(deg) ------
__global__ void k_scanA(int n) {
    __shared__ int s[32];
    int i = blockIdx.x * 1024 + threadIdx.x;
    int c = (i < n) ? g_count[i] : 0;
    if (i < n) g_dinv[i] = rsqrtf(g_dinv[i]);   // fused (deg >= 1 always)
    int v = c;
    #pragma unroll
    for (int o = 16; o > 0; o >>= 1) v += __shfl_down_sync(0xFFFFFFFFu, v, o);
    int lane = threadIdx.x & 31, wid = threadIdx.x >> 5;
    if (lane == 0) s[wid] = v;
    __syncthreads();
    if (wid == 0) {
        int v2 = s[lane];
        #pragma unroll
        for (int o = 16; o > 0; o >>= 1) v2 += __shfl_down_sync(0xFFFFFFFFu, v2, o);
        if (lane == 0) g_bsum[blockIdx.x] = v2;
    }
}

// ---------------- scan step B: exclusive scan of block sums (nb <= 256) ----
__global__ void k_scanB(int nb) {
    __shared__ int sh[256];
    int t = threadIdx.x;
    int v = (t < nb) ? g_bsum[t] : 0;
    sh[t] = v;
    __syncthreads();
    for (int o = 1; o < 256; o <<= 1) {
        int u = (t >= o) ? sh[t - o] : 0;
        __syncthreads();
        sh[t] += u;
        __syncthreads();
    }
    if (t < nb) g_bsum[t] = sh[t] - v;   // exclusive
}

// ---------------- scan step C: full exclusive scan -> rowptr; reset counts -
__global__ void k_scanC(int n) {
    __shared__ int ws[32];
    int i = blockIdx.x * 1024 + threadIdx.x;
    int c = (i < n) ? g_count[i] : 0;
    int lane = threadIdx.x & 31, wid = threadIdx.x >> 5;
    int inc = c;
    #pragma unroll
    for (int o = 1; o < 32; o <<= 1) {
        int t = __shfl_up_sync(0xFFFFFFFFu, inc, o);
        if (lane >= o) inc += t;
    }
    if (lane == 31) ws[wid] = inc;
    __syncthreads();
    if (wid == 0) {
        int v = ws[lane];
        #pragma unroll
        for (int o = 1; o < 32; o <<= 1) {
            int t = __shfl_up_sync(0xFFFFFFFFu, v, o);
            if (lane >= o) v += t;
        }
        ws[lane] = v;
    }
    __syncthreads();
    int base = (wid > 0) ? ws[wid - 1] : 0;
    int excl = base + inc - c + g_bsum[blockIdx.x];
    if (i < n) {
        g_rowptr[i] = excl;
        g_count[i] = 0;                     // reuse as placement cursor
        if (i == n - 1) g_rowptr[n] = excl + c;
    }
}

// ---------------- pass 2 over edges: place packed (src,norm) into CSR ------
__global__ void k_place(const int* __restrict__ src, const int* __restrict__ dst,
                        const float* __restrict__ w, int e) {
    int i = blockIdx.x * blockDim.x + threadIdx.x;
    if (i < e) {
        int s = src[i], d = dst[i];
        int pos = g_rowptr[d] + atomicAdd(&g_count[d], 1);
        float nw = g_dinv[s] * w[i] * g_dinv[d];
        g_edge[pos] = make_uint2((uint32_t)s, __float_as_uint(nw));
    }
}

// ---------------- GEMM: h = x @ W via TF32 mma.sync, fp16 output -----------
__device__ __forceinline__ uint32_t f2tf32(float f) {
    uint32_t r;
    asm("cvt.rna.tf32.f32 %0, %1;" : "=r"(r) : "f"(f));
    return r;
}

#define BM  64
#define KCH 32
#define AST 36    // A smem row stride: (36*r + k) % 32 distinct
#define WST 136   // W smem row stride: (136*k + n) % 32 distinct

__global__ void __launch_bounds__(256) k_gemm(const float* __restrict__ x,
                                              const float* __restrict__ W, int n) {
    __shared__ uint32_t As[BM * AST];     // 64 x 32 tf32 (padded)
    __shared__ uint32_t Ws[KCH * WST];    // 32 x 128 tf32 (padded)
    int tid = threadIdx.x;
    int lane = tid & 31, wid = tid >> 5;
    int warpM = wid & 3, warpN = wid >> 2;
    int row0 = blockIdx.x * BM;
    int qr = lane >> 2;                   // quad row 0..7
    int qk = lane & 3;                    // quad k   0..3

    float c[8][4];
    #pragma unroll
    for (int t = 0; t < 8; t++)
        #pragma unroll
        for (int j = 0; j < 4; j++) c[t][j] = 0.0f;

    for (int kc = 0; kc < FD; kc += KCH) {
        __syncthreads();
        #pragma unroll
        for (int i = tid; i < BM * KCH; i += 256) {
            int r = i >> 5, k = i & 31;
            int gr = row0 + r;
            float v = (gr < n) ? x[(size_t)gr * FD + kc + k] : 0.0f;
            As[r * AST + k] = f2tf32(v);
        }
        #pragma unroll
        for (int i = tid; i < KCH * FD; i += 256) {
            int k = i >> 7, nn = i & 127;
            Ws[k * WST + nn] = f2tf32(W[(size_t)(kc + k) * FD + nn]);
        }
        __syncthreads();

        #pragma unroll
        for (int kk = 0; kk < KCH; kk += 8) {
            int ar = warpM * 16 + qr;
            uint32_t a0 = As[ar * AST + kk + qk];
            uint32_t a1 = As[(ar + 8) * AST + kk + qk];
            uint32_t a2 = As[ar * AST + kk + qk + 4];
            uint32_t a3 = As[(ar + 8) * AST + kk + qk + 4];
            #pragma unroll
            for (int t = 0; t < 8; t++) {
                int bn = warpN * 64 + t * 8 + qr;
                uint32_t b0 = Ws[(kk + qk) * WST + bn];
                uint32_t b1 = Ws[(kk + qk + 4) * WST + bn];
                asm volatile(
                    "mma.sync.aligned.m16n8k8.row.col.f32.tf32.tf32.f32 "
                    "{%0,%1,%2,%3}, {%4,%5,%6,%7}, {%8,%9}, {%0,%1,%2,%3};"
                    : "+f"(c[t][0]), "+f"(c[t][1]), "+f"(c[t][2]), "+f"(c[t][3])
                    : "r"(a0), "r"(a1), "r"(a2), "r"(a3), "r"(b0), "r"(b1));
            }
        }
    }

    int mr = row0 + warpM * 16 + qr;
    #pragma unroll
    for (int t = 0; t < 8; t++) {
        int col = warpN * 64 + t * 8 + 2 * qk;
        if (mr < n)
            *(__half2*)&g_h[(size_t)mr * FD + col] = __floats2half2_rn(c[t][0], c[t][1]);
        if (mr + 8 < n)
            *(__half2*)&g_h[(size_t)(mr + 8) * FD + col] = __floats2half2_rn(c[t][2], c[t][3]);
    }
}

// ---------------- gather: one warp per dst node, MLP-4 inner loop ----------
__device__ __forceinline__ void fma_row(float4& acc, uint2 raw, float nw) {
    __half2 h0 = *reinterpret_cast<__half2*>(&raw.x);
    __half2 h1 = *reinterpret_cast<__half2*>(&raw.y);
    float2 f0 = __half22float2(h0), f1 = __half22float2(h1);
    acc.x += f0.x * nw; acc.y += f0.y * nw;
    acc.z += f1.x * nw; acc.w += f1.y * nw;
}

__device__ __forceinline__ void stream_f4(float* p, float4 v) {
    asm volatile("st.global.cs.v4.f32 [%0], {%1,%2,%3,%4};"
                 :: "l"(p), "f"(v.x), "f"(v.y), "f"(v.z), "f"(v.w) : "memory");
}

__global__ void __launch_bounds__(256) k_gather(const float* __restrict__ b,
                                                float* __restrict__ out, int n) {
    int warp = (blockIdx.x * blockDim.x + threadIdx.x) >> 5;
    int lane = threadIdx.x & 31;
    if (warp >= n) return;
    int beg = g_rowptr[warp], end = g_rowptr[warp + 1];
    float4 acc = make_float4(0.f, 0.f, 0.f, 0.f);
    size_t loff = (size_t)lane * 4;

    int e = beg;
    // 4-wide: 4 independent edge-record loads, then 4 independent row loads
    for (; e + 4 <= end; e += 4) {
        uint2 p0 = g_edge[e + 0];
        uint2 p1 = g_edge[e + 1];
        uint2 p2 = g_edge[e + 2];
        uint2 p3 = g_edge[e + 3];
        uint2 r0 = *(const uint2*)&g_h[(size_t)p0.x * FD + loff];
        uint2 r1 = *(const uint2*)&g_h[(size_t)p1.x * FD + loff];
        uint2 r2 = *(const uint2*)&g_h[(size_t)p2.x * FD + loff];
        uint2 r3 = *(const uint2*)&g_h[(size_t)p3.x * FD + loff];
        fma_row(acc, r0, __uint_as_float(p0.y));
        fma_row(acc, r1, __uint_as_float(p1.y));
        fma_row(acc, r2, __uint_as_float(p2.y));
        fma_row(acc, r3, __uint_as_float(p3.y));
    }
    for (; e < end; e++) {
        uint2 p = g_edge[e];
        uint2 r = *(const uint2*)&g_h[(size_t)p.x * FD + loff];
        fma_row(acc, r, __uint_as_float(p.y));
    }

    // self-loop: norm = dinv[i]^2, then + bias
    float di = g_dinv[warp];
    uint2 raw = *(const uint2*)&g_h[(size_t)warp * FD + loff];
    fma_row(acc, raw, di * di);
    float4 bv = *(const float4*)&b[lane * 4];
    acc.x += bv.x; acc.y += bv.y; acc.z += bv.z; acc.w += bv.w;

    size_t off = (size_t)warp * FD + loff;
    stream_f4(&out[off], acc);
    float4 rv = make_float4(fmaxf(acc.x, 0.f), fmaxf(acc.y, 0.f),
                            fmaxf(acc.z, 0.f), fmaxf(acc.w, 0.f));
    stream_f4(&out[(size_t)n * FD + off], rv);
}

// ---------------- launcher -------------------------------------------------
static cudaStream_t g_s2 = nullptr;
static cudaEvent_t  g_evFork = nullptr, g_evJoin = nullptr;

extern "C" void kernel_launch(void* const* d_in, const int* in_sizes, int n_in,
                              void* d_out, int out_size) {
    (void)n_in; (void)out_size;
    const float* x  = (const float*)d_in[0];
    const float* W  = (const float*)d_in[1];
    const float* b  = (const float*)d_in[2];
    // d_in[3] = level (scalar, always 0) — ignored
    const int*   ei = (const int*)d_in[4];
    const float* ew = (const float*)d_in[5];

    int n = in_sizes[0] / FD;
    int e = in_sizes[4] / 2;
    const int* src = ei;
    const int* dst = ei + e;

    if (g_s2 == nullptr) {   // one-time resource setup (first call = correctness run)
        cudaStreamCreateWithFlags(&g_s2, cudaStreamNonBlocking);
        cudaEventCreateWithFlags(&g_evFork, cudaEventDisableTiming);
        cudaEventCreateWithFlags(&g_evJoin, cudaEventDisableTiming);
    }

    // fork: GEMM runs on g_s2 concurrently with the edge/CSR pipeline
    cudaEventRecord(g_evFork, 0);
    cudaStreamWaitEvent(g_s2, g_evFork, 0);
    k_gemm<<<(n + BM - 1) / BM, 256, 0, g_s2>>>(x, W, n);
    cudaEventRecord(g_evJoin, g_s2);

    // edge / CSR pipeline on the default stream
    k_init  <<<(n + 255) / 256, 256>>>(n);
    k_deg   <<<(e + 255) / 256, 256>>>(src, dst, ew, e);

    int nb = (n + 1023) / 1024;
    k_scanA <<<nb, 1024>>>(n);
    k_scanB <<<1, 256>>>(nb);
    k_scanC <<<nb, 1024>>>(n);

    k_place <<<(e + 255) / 256, 256>>>(src, dst, ew, e);

    // join: gather needs both h and the CSR
    cudaStreamWaitEvent(0, g_evJoin, 0);
    k_gather<<<(n * 32 + 255) / 256, 256>>>(b, (float*)d_out, n);
}

// round 7
// speedup vs baseline: 2.0448x; 1.0409x over previous
#include <cuda_runtime.h>
#include <cuda_fp16.h>
#include <cstdint>

#define FD 128          // feature dim (in == out == 128)
#define NMAX 100000
#define EMAX 1600000

#define WFIX 1048576.0f           // 2^20 fixed-point scale for edge weights
#define ACC_MASK ((1ULL << 40) - 1ULL)

// ---------------- scratch (static device globals; no allocation allowed) ----
__device__ __half g_h[(size_t)NMAX * FD];           // x @ W (fp16 store)
__device__ unsigned long long g_acc[NMAX];          // (count<<40)|fixed20(sum w)
__device__ float g_dinv[NMAX];                      // rsqrt(deg)
__device__ int   g_rowptr[NMAX];                    // CSR starts -> cursors
__device__ int   g_bsum[256];                       // scan block sums
__device__ uint2 g_edge[EMAX];                      // CSR: packed (src, norm)

// ---------------- pass 1 over edges: fused degree + histogram (1 atomic) ---
__global__ void k_deg(const int* __restrict__ dst, const float* __restrict__ w,
                      int e) {
    int i = (blockIdx.x * blockDim.x + threadIdx.x) * 4;
    if (i + 4 <= e) {
        int4   d  = *(const int4*)&dst[i];
        float4 ww = *(const float4*)&w[i];
        atomicAdd(&g_acc[d.x], (1ULL << 40) | (unsigned long long)(ww.x * WFIX + 0.5f));
        atomicAdd(&g_acc[d.y], (1ULL << 40) | (unsigned long long)(ww.y * WFIX + 0.5f));
        atomicAdd(&g_acc[d.z], (1ULL << 40) | (unsigned long long)(ww.z * WFIX + 0.5f));
        atomicAdd(&g_acc[d.w], (1ULL << 40) | (unsigned long long)(ww.w * WFIX + 0.5f));
    } else {
        for (int j = i; j < e; j++)
            atomicAdd(&g_acc[dst[j]],
                      (1ULL << 40) | (unsigned long long)(w[j] * WFIX + 0.5f));
    }
}

// ---------------- scan step A: per-block count sums; dinv = rsqrt(deg) -----
__global__ void k_scanA(int n) {
    __shared__ int s[32];
    int i = blockIdx.x * 1024 + threadIdx.x;
    int c = 0;
    if (i < n) {
        unsigned long long acc = g_acc[i];
        c = (int)(acc >> 40);
        float deg = (float)(acc & ACC_MASK) * (1.0f / WFIX) + 1.0f;  // +1 self-loop
        g_dinv[i] = rsqrtf(deg);
    }
    int v = c;
    #pragma unroll
    for (int o = 16; o > 0; o >>= 1) v += __shfl_down_sync(0xFFFFFFFFu, v, o);
    int lane = threadIdx.x & 31, wid = threadIdx.x >> 5;
    if (lane == 0) s[wid] = v;
    __syncthreads();
    if (wid == 0) {
        int v2 = s[lane];
        #pragma unroll
        for (int o = 16; o > 0; o >>= 1) v2 += __shfl_down_sync(0xFFFFFFFFu, v2, o);
        if (lane == 0) g_bsum[blockIdx.x] = v2;
    }
}

// ---------------- scan step B: exclusive scan of block sums (nb <= 256) ----
__global__ void k_scanB(int nb) {
    __shared__ int sh[256];
    int t = threadIdx.x;
    int v = (t < nb) ? g_bsum[t] : 0;
    sh[t] = v;
    __syncthreads();
    for (int o = 1; o < 256; o <<= 1) {
        int u = (t >= o) ? sh[t - o] : 0;
        __syncthreads();
        sh[t] += u;
        __syncthreads();
    }
    if (t < nb) g_bsum[t] = sh[t] - v;   // exclusive
}

// ---------------- scan step C: rowptr = exclusive scan; reset g_acc --------
__global__ void k_scanC(int n) {
    __shared__ int ws[32];
    int i = blockIdx.x * 1024 + threadIdx.x;
    int c = 0;
    if (i < n) {
        c = (int)(g_acc[i] >> 40);
        g_acc[i] = 0ULL;                 // ready for next graph replay
    }
    int lane = threadIdx.x & 31, wid = threadIdx.x >> 5;
    int inc = c;
    #pragma unroll
    for (int o = 1; o < 32; o <<= 1) {
        int t = __shfl_up_sync(0xFFFFFFFFu, inc, o);
        if (lane >= o) inc += t;
    }
    if (lane == 31) ws[wid] = inc;
    __syncthreads();
    if (wid == 0) {
        int v = ws[lane];
        #pragma unroll
        for (int o = 1; o < 32; o <<= 1) {
            int t = __shfl_up_sync(0xFFFFFFFFu, v, o);
            if (lane >= o) v += t;
        }
        ws[lane] = v;
    }
    __syncthreads();
    int base = (wid > 0) ? ws[wid - 1] : 0;
    if (i < n) g_rowptr[i] = base + inc - c + g_bsum[blockIdx.x];  // start
}

// ---------------- pass 2: place packed (src,norm); rowptr doubles as cursor
// After this kernel: g_rowptr[d] = start[d] + count[d] = start[d+1].
__global__ void k_place(const int* __restrict__ src, const int* __restrict__ dst,
                        const float* __restrict__ w, int e) {
    int i = (blockIdx.x * blockDim.x + threadIdx.x) * 4;
    if (i + 4 <= e) {
        int4   s4 = *(const int4*)&src[i];
        int4   d4 = *(const int4*)&dst[i];
        float4 w4 = *(const float4*)&w[i];
        #pragma unroll
        for (int j = 0; j < 4; j++) {
            int s = (&s4.x)[j], d = (&d4.x)[j];
            float nw = g_dinv[s] * (&w4.x)[j] * g_dinv[d];
            int pos = atomicAdd(&g_rowptr[d], 1);
            g_edge[pos] = make_uint2((uint32_t)s, __float_as_uint(nw));
        }
    } else {
        for (int j = i; j < e; j++) {
            int s = src[j], d = dst[j];
            float nw = g_dinv[s] * w[j] * g_dinv[d];
            int pos = atomicAdd(&g_rowptr[d], 1);
            g_edge[pos] = make_uint2((uint32_t)s, __float_as_uint(nw));
        }
    }
}

// ---------------- GEMM: h = x @ W via TF32 mma.sync, fp16 output -----------
__device__ __forceinline__ uint32_t f2tf32(float f) {
    uint32_t r;
    asm("cvt.rna.tf32.f32 %0, %1;" : "=r"(r) : "f"(f));
    return r;
}

#define BM  64
#define KCH 32
#define AST 36
#define WST 136

__global__ void __launch_bounds__(256) k_gemm(const float* __restrict__ x,
                                              const float* __restrict__ W, int n) {
    __shared__ uint32_t As[BM * AST];
    __shared__ uint32_t Ws[KCH * WST];
    int tid = threadIdx.x;
    int lane = tid & 31, wid = tid >> 5;
    int warpM = wid & 3, warpN = wid >> 2;
    int row0 = blockIdx.x * BM;
    int qr = lane >> 2;
    int qk = lane & 3;

    float c[8][4];
    #pragma unroll
    for (int t = 0; t < 8; t++)
        #pragma unroll
        for (int j = 0; j < 4; j++) c[t][j] = 0.0f;

    for (int kc = 0; kc < FD; kc += KCH) {
        __syncthreads();
        #pragma unroll
        for (int i = tid; i < BM * KCH; i += 256) {
            int r = i >> 5, k = i & 31;
            int gr = row0 + r;
            float v = (gr < n) ? x[(size_t)gr * FD + kc + k] : 0.0f;
            As[r * AST + k] = f2tf32(v);
        }
        #pragma unroll
        for (int i = tid; i < KCH * FD; i += 256) {
            int k = i >> 7, nn = i & 127;
            Ws[k * WST + nn] = f2tf32(W[(size_t)(kc + k) * FD + nn]);
        }
        __syncthreads();

        #pragma unroll
        for (int kk = 0; kk < KCH; kk += 8) {
            int ar = warpM * 16 + qr;
            uint32_t a0 = As[ar * AST + kk + qk];
            uint32_t a1 = As[(ar + 8) * AST + kk + qk];
            uint32_t a2 = As[ar * AST + kk + qk + 4];
            uint32_t a3 = As[(ar + 8) * AST + kk + qk + 4];
            #pragma unroll
            for (int t = 0; t < 8; t++) {
                int bn = warpN * 64 + t * 8 + qr;
                uint32_t b0 = Ws[(kk + qk) * WST + bn];
                uint32_t b1 = Ws[(kk + qk + 4) * WST + bn];
                asm volatile(
                    "mma.sync.aligned.m16n8k8.row.col.f32.tf32.tf32.f32 "
                    "{%0,%1,%2,%3}, {%4,%5,%6,%7}, {%8,%9}, {%0,%1,%2,%3};"
                    : "+f"(c[t][0]), "+f"(c[t][1]), "+f"(c[t][2]), "+f"(c[t][3])
                    : "r"(a0), "r"(a1), "r"(a2), "r"(a3), "r"(b0), "r"(b1));
            }
        }
    }

    int mr = row0 + warpM * 16 + qr;
    #pragma unroll
    for (int t = 0; t < 8; t++) {
        int col = warpN * 64 + t * 8 + 2 * qk;
        if (mr < n)
            *(__half2*)&g_h[(size_t)mr * FD + col] = __floats2half2_rn(c[t][0], c[t][1]);
        if (mr + 8 < n)
            *(__half2*)&g_h[(size_t)(mr + 8) * FD + col] = __floats2half2_rn(c[t][2], c[t][3]);
    }
}

// ---------------- gather: one warp per dst node, MLP-8 inner loop ----------
__device__ __forceinline__ void fma_row(float4& acc, uint2 raw, float nw) {
    __half2 h0 = *reinterpret_cast<__half2*>(&raw.x);
    __half2 h1 = *reinterpret_cast<__half2*>(&raw.y);
    float2 f0 = __half22float2(h0), f1 = __half22float2(h1);
    acc.x += f0.x * nw; acc.y += f0.y * nw;
    acc.z += f1.x * nw; acc.w += f1.y * nw;
}

__device__ __forceinline__ void stream_f4(float* p, float4 v) {
    asm volatile("st.global.cs.v4.f32 [%0], {%1,%2,%3,%4};"
                 :: "l"(p), "f"(v.x), "f"(v.y), "f"(v.z), "f"(v.w) : "memory");
}

__global__ void __launch_bounds__(256) k_gather(const float* __restrict__ b,
                                                float* __restrict__ out, int n) {
    int warp = (blockIdx.x * blockDim.x + threadIdx.x) >> 5;
    int lane = threadIdx.x & 31;
    if (warp >= n) return;
    // rowptr was consumed as cursor: rowptr[d] is now END of segment d
    int beg = (warp == 0) ? 0 : g_rowptr[warp - 1];
    int end = g_rowptr[warp];
    float4 acc = make_float4(0.f, 0.f, 0.f, 0.f);
    size_t loff = (size_t)lane * 4;

    int e = beg;
    for (; e + 8 <= end; e += 8) {
        uint2 p[8], r[8];
        #pragma unroll
        for (int j = 0; j < 8; j++) p[j] = g_edge[e + j];
        #pragma unroll
        for (int j = 0; j < 8; j++)
            r[j] = *(const uint2*)&g_h[(size_t)p[j].x * FD + loff];
        #pragma unroll
        for (int j = 0; j < 8; j++)
            fma_row(acc, r[j], __uint_as_float(p[j].y));
    }
    for (; e + 2 <= end; e += 2) {
        uint2 p0 = g_edge[e], p1 = g_edge[e + 1];
        uint2 r0 = *(const uint2*)&g_h[(size_t)p0.x * FD + loff];
        uint2 r1 = *(const uint2*)&g_h[(size_t)p1.x * FD + loff];
        fma_row(acc, r0, __uint_as_float(p0.y));
        fma_row(acc, r1, __uint_as_float(p1.y));
    }
    if (e < end) {
        uint2 p = g_edge[e];
        uint2 r = *(const uint2*)&g_h[(size_t)p.x * FD + loff];
        fma_row(acc, r, __uint_as_float(p.y));
    }

    // self-loop: norm = dinv^2, then + bias
    float di = g_dinv[warp];
    uint2 raw = *(const uint2*)&g_h[(size_t)warp * FD + loff];
    fma_row(acc, raw, di * di);
    float4 bv = *(const float4*)&b[lane * 4];
    acc.x += bv.x; acc.y += bv.y; acc.z += bv.z; acc.w += bv.w;

    size_t off = (size_t)warp * FD + loff;
    stream_f4(&out[off], acc);
    float4 rv = make_float4(fmaxf(acc.x, 0.f), fmaxf(acc.y, 0.f),
                            fmaxf(acc.z, 0.f), fmaxf(acc.w, 0.f));
    stream_f4(&out[(size_t)n * FD + off], rv);
}

// ---------------- launcher -------------------------------------------------
static cudaStream_t g_s2 = nullptr;
static cudaEvent_t  g_evFork = nullptr, g_evJoin = nullptr;

extern "C" void kernel_launch(void* const* d_in, const int* in_sizes, int n_in,
                              void* d_out, int out_size) {
    (void)n_in; (void)out_size;
    const float* x  = (const float*)d_in[0];
    const float* W  = (const float*)d_in[1];
    const float* b  = (const float*)d_in[2];
    // d_in[3] = level (scalar, always 0) — ignored
    const int*   ei = (const int*)d_in[4];
    const float* ew = (const float*)d_in[5];

    int n = in_sizes[0] / FD;
    int e = in_sizes[4] / 2;
    const int* src = ei;
    const int* dst = ei + e;

    if (g_s2 == nullptr) {
        cudaStreamCreateWithFlags(&g_s2, cudaStreamNonBlocking);
        cudaEventCreateWithFlags(&g_evFork, cudaEventDisableTiming);
        cudaEventCreateWithFlags(&g_evJoin, cudaEventDisableTiming);
    }

    // fork: GEMM runs on g_s2 concurrently with the edge/CSR pipeline
    cudaEventRecord(g_evFork, 0);
    cudaStreamWaitEvent(g_s2, g_evFork, 0);
    k_gemm<<<(n + BM - 1) / BM, 256, 0, g_s2>>>(x, W, n);
    cudaEventRecord(g_evJoin, g_s2);

    // edge / CSR pipeline on the default stream (g_acc is zero by invariant)
    int e4 = (e + 1023) / 1024;          // blocks of 256 threads x 4 edges
    k_deg   <<<e4, 256>>>(dst, ew, e);

    int nb = (n + 1023) / 1024;
    k_scanA <<<nb, 1024>>>(n);
    k_scanB <<<1, 256>>>(nb);
    k_scanC <<<nb, 1024>>>(n);

    k_place <<<e4, 256>>>(src, dst, ew, e);

    // join: gather needs both h and the CSR
    cudaStreamWaitEvent(0, g_evJoin, 0);
    k_gather<<<(n * 32 + 255) / 256, 256>>>(b, (float*)d_out, n);
}

// round 8
// speedup vs baseline: 2.0844x; 1.0194x over previous
#include <cuda_runtime.h>
#include <cuda_fp16.h>
#include <cstdint>

#define FD 128          // feature dim (in == out == 128)
#define NMAX 100000
#define EMAX 1600000

#define WFIX 1048576.0f           // 2^20 fixed-point scale for edge weights
#define ACC_MASK ((1ULL << 40) - 1ULL)

// ---------------- scratch (static device globals; no allocation allowed) ----
__device__ __half g_h[(size_t)NMAX * FD];           // x @ W (fp16 store)
__device__ unsigned long long g_acc[NMAX];          // (count<<40)|fixed20(sum w); 0 by invariant
__device__ float g_dinv[NMAX];                      // rsqrt(deg)
__device__ int   g_start[NMAX];                     // CSR segment start
__device__ int   g_cur[NMAX];                       // placement cursor -> segment end
__device__ uint2 g_edge[EMAX];                      // CSR: packed (src, norm)
__device__ unsigned int g_total;                    // arrival-ordered base; 0 by invariant
__device__ unsigned int g_done;                     // block-done counter; 0 by invariant

// ---------------- pass 1 over edges: fused degree + histogram (1 atomic) ---
__global__ void k_deg(const int* __restrict__ dst, const float* __restrict__ w,
                      int e) {
    int i = (blockIdx.x * blockDim.x + threadIdx.x) * 4;
    if (i + 4 <= e) {
        int4   d  = __ldcs((const int4*)&dst[i]);     // streamed: read once
        float4 ww = __ldcs((const float4*)&w[i]);
        atomicAdd(&g_acc[d.x], (1ULL << 40) | (unsigned long long)(ww.x * WFIX + 0.5f));
        atomicAdd(&g_acc[d.y], (1ULL << 40) | (unsigned long long)(ww.y * WFIX + 0.5f));
        atomicAdd(&g_acc[d.z], (1ULL << 40) | (unsigned long long)(ww.z * WFIX + 0.5f));
        atomicAdd(&g_acc[d.w], (1ULL << 40) | (unsigned long long)(ww.w * WFIX + 0.5f));
    } else {
        for (int j = i; j < e; j++)
            atomicAdd(&g_acc[dst[j]],
                      (1ULL << 40) | (unsigned long long)(w[j] * WFIX + 0.5f));
    }
}

// ---------------- single-kernel scan: dinv + arrival-ordered CSR offsets ---
// Segment order in g_edge is arbitrary (arrival order of blocks); gather uses
// explicit g_start/g_cur so no cross-node monotonicity is required.
__global__ void __launch_bounds__(1024) k_scan(int n, int nb) {
    __shared__ int ws[32];
    __shared__ int s_base;
    int tid = threadIdx.x;
    int i = blockIdx.x * 1024 + tid;
    int c = 0;
    if (i < n) {
        unsigned long long a = g_acc[i];
        c = (int)(a >> 40);
        float deg = (float)(a & ACC_MASK) * (1.0f / WFIX) + 1.0f;   // +1 self-loop
        g_dinv[i] = rsqrtf(deg);
        g_acc[i] = 0ULL;                 // restore invariant for next replay
    }
    int lane = tid & 31, wid = tid >> 5;
    int inc = c;
    #pragma unroll
    for (int o = 1; o < 32; o <<= 1) {
        int t = __shfl_up_sync(0xFFFFFFFFu, inc, o);
        if (lane >= o) inc += t;
    }
    if (lane == 31) ws[wid] = inc;
    __syncthreads();
    if (wid == 0) {
        int v = ws[lane];
        #pragma unroll
        for (int o = 1; o < 32; o <<= 1) {
            int t = __shfl_up_sync(0xFFFFFFFFu, v, o);
            if (lane >= o) v += t;
        }
        ws[lane] = v;
    }
    __syncthreads();
    int incl = ((wid > 0) ? ws[wid - 1] : 0) + inc;   // block-inclusive
    if (tid == 1023)                                  // holds the block total
        s_base = (int)atomicAdd(&g_total, (unsigned)incl);
    __syncthreads();
    if (i < n) {
        int start = s_base + incl - c;
        g_start[i] = start;
        g_cur[i]   = start;
    }
    __syncthreads();
    if (tid == 0 && atomicAdd(&g_done, 1u) == (unsigned)(nb - 1)) {
        g_total = 0u;                    // self-clean for next replay
        g_done  = 0u;
    }
}

// ---------------- pass 2: place packed (src,norm) via g_cur cursor ---------
__global__ void k_place(const int* __restrict__ src, const int* __restrict__ dst,
                        const float* __restrict__ w, int e) {
    int i = (blockIdx.x * blockDim.x + threadIdx.x) * 4;
    if (i + 4 <= e) {
        int4   s4 = __ldcs((const int4*)&src[i]);
        int4   d4 = __ldcs((const int4*)&dst[i]);
        float4 w4 = __ldcs((const float4*)&w[i]);
        #pragma unroll
        for (int j = 0; j < 4; j++) {
            int s = (&s4.x)[j], d = (&d4.x)[j];
            float nw = g_dinv[s] * (&w4.x)[j] * g_dinv[d];
            int pos = atomicAdd(&g_cur[d], 1);
            g_edge[pos] = make_uint2((uint32_t)s, __float_as_uint(nw));
        }
    } else {
        for (int j = i; j < e; j++) {
            int s = src[j], d = dst[j];
            float nw = g_dinv[s] * w[j] * g_dinv[d];
            int pos = atomicAdd(&g_cur[d], 1);
            g_edge[pos] = make_uint2((uint32_t)s, __float_as_uint(nw));
        }
    }
}

// ---------------- GEMM: h = x @ W via TF32 mma.sync, fp16 output -----------
__device__ __forceinline__ uint32_t f2tf32(float f) {
    uint32_t r;
    asm("cvt.rna.tf32.f32 %0, %1;" : "=r"(r) : "f"(f));
    return r;
}

#define BM  64
#define KCH 32
#define AST 36
#define WST 136

__global__ void __launch_bounds__(256) k_gemm(const float* __restrict__ x,
                                              const float* __restrict__ W, int n) {
    __shared__ uint32_t As[BM * AST];
    __shared__ uint32_t Ws[KCH * WST];
    int tid = threadIdx.x;
    int lane = tid & 31, wid = tid >> 5;
    int warpM = wid & 3, warpN = wid >> 2;
    int row0 = blockIdx.x * BM;
    int qr = lane >> 2;
    int qk = lane & 3;

    float c[8][4];
    #pragma unroll
    for (int t = 0; t < 8; t++)
        #pragma unroll
        for (int j = 0; j < 4; j++) c[t][j] = 0.0f;

    for (int kc = 0; kc < FD; kc += KCH) {
        __syncthreads();
        #pragma unroll
        for (int i = tid; i < BM * KCH; i += 256) {
            int r = i >> 5, k = i & 31;
            int gr = row0 + r;
            float v = (gr < n) ? x[(size_t)gr * FD + kc + k] : 0.0f;
            As[r * AST + k] = f2tf32(v);
        }
        #pragma unroll
        for (int i = tid; i < KCH * FD; i += 256) {
            int k = i >> 7, nn = i & 127;
            Ws[k * WST + nn] = f2tf32(W[(size_t)(kc + k) * FD + nn]);
        }
        __syncthreads();

        #pragma unroll
        for (int kk = 0; kk < KCH; kk += 8) {
            int ar = warpM * 16 + qr;
            uint32_t a0 = As[ar * AST + kk + qk];
            uint32_t a1 = As[(ar + 8) * AST + kk + qk];
            uint32_t a2 = As[ar * AST + kk + qk + 4];
            uint32_t a3 = As[(ar + 8) * AST + kk + qk + 4];
            #pragma unroll
            for (int t = 0; t < 8; t++) {
                int bn = warpN * 64 + t * 8 + qr;
                uint32_t b0 = Ws[(kk + qk) * WST + bn];
                uint32_t b1 = Ws[(kk + qk + 4) * WST + bn];
                asm volatile(
                    "mma.sync.aligned.m16n8k8.row.col.f32.tf32.tf32.f32 "
                    "{%0,%1,%2,%3}, {%4,%5,%6,%7}, {%8,%9}, {%0,%1,%2,%3};"
                    : "+f"(c[t][0]), "+f"(c[t][1]), "+f"(c[t][2]), "+f"(c[t][3])
                    : "r"(a0), "r"(a1), "r"(a2), "r"(a3), "r"(b0), "r"(b1));
            }
        }
    }

    int mr = row0 + warpM * 16 + qr;
    #pragma unroll
    for (int t = 0; t < 8; t++) {
        int col = warpN * 64 + t * 8 + 2 * qk;
        if (mr < n)
            *(__half2*)&g_h[(size_t)mr * FD + col] = __floats2half2_rn(c[t][0], c[t][1]);
        if (mr + 8 < n)
            *(__half2*)&g_h[(size_t)(mr + 8) * FD + col] = __floats2half2_rn(c[t][2], c[t][3]);
    }
}

// ---------------- gather: one warp per dst node, MLP-8 inner loop ----------
__device__ __forceinline__ void fma_row(float4& acc, uint2 raw, float nw) {
    __half2 h0 = *reinterpret_cast<__half2*>(&raw.x);
    __half2 h1 = *reinterpret_cast<__half2*>(&raw.y);
    float2 f0 = __half22float2(h0), f1 = __half22float2(h1);
    acc.x += f0.x * nw; acc.y += f0.y * nw;
    acc.z += f1.x * nw; acc.w += f1.y * nw;
}

__device__ __forceinline__ void stream_f4(float* p, float4 v) {
    asm volatile("st.global.cs.v4.f32 [%0], {%1,%2,%3,%4};"
                 :: "l"(p), "f"(v.x), "f"(v.y), "f"(v.z), "f"(v.w) : "memory");
}

__global__ void __launch_bounds__(256) k_gather(const float* __restrict__ b,
                                                float* __restrict__ out, int n) {
    int warp = (blockIdx.x * blockDim.x + threadIdx.x) >> 5;
    int lane = threadIdx.x & 31;
    if (warp >= n) return;
    int beg = g_start[warp];
    int end = g_cur[warp];                // == start + count after k_place
    float4 acc = make_float4(0.f, 0.f, 0.f, 0.f);
    size_t loff = (size_t)lane * 4;

    int e = beg;
    for (; e + 8 <= end; e += 8) {
        uint2 p[8], r[8];
        #pragma unroll
        for (int j = 0; j < 8; j++) p[j] = __ldcs(&g_edge[e + j]);   // streamed
        #pragma unroll
        for (int j = 0; j < 8; j++)
            r[j] = *(const uint2*)&g_h[(size_t)p[j].x * FD + loff];
        #pragma unroll
        for (int j = 0; j < 8; j++)
            fma_row(acc, r[j], __uint_as_float(p[j].y));
    }
    for (; e + 2 <= end; e += 2) {
        uint2 p0 = __ldcs(&g_edge[e]), p1 = __ldcs(&g_edge[e + 1]);
        uint2 r0 = *(const uint2*)&g_h[(size_t)p0.x * FD + loff];
        uint2 r1 = *(const uint2*)&g_h[(size_t)p1.x * FD + loff];
        fma_row(acc, r0, __uint_as_float(p0.y));
        fma_row(acc, r1, __uint_as_float(p1.y));
    }
    if (e < end) {
        uint2 p = __ldcs(&g_edge[e]);
        uint2 r = *(const uint2*)&g_h[(size_t)p.x * FD + loff];
        fma_row(acc, r, __uint_as_float(p.y));
    }

    // self-loop: norm = dinv^2, then + bias
    float di = g_dinv[warp];
    uint2 raw = *(const uint2*)&g_h[(size_t)warp * FD + loff];
    fma_row(acc, raw, di * di);
    float4 bv = *(const float4*)&b[lane * 4];
    acc.x += bv.x; acc.y += bv.y; acc.z += bv.z; acc.w += bv.w;

    size_t off = (size_t)warp * FD + loff;
    stream_f4(&out[off], acc);
    float4 rv = make_float4(fmaxf(acc.x, 0.f), fmaxf(acc.y, 0.f),
                            fmaxf(acc.z, 0.f), fmaxf(acc.w, 0.f));
    stream_f4(&out[(size_t)n * FD + off], rv);
}

// ---------------- launcher -------------------------------------------------
static cudaStream_t g_s2 = nullptr;
static cudaEvent_t  g_evFork = nullptr, g_evJoin = nullptr;

extern "C" void kernel_launch(void* const* d_in, const int* in_sizes, int n_in,
                              void* d_out, int out_size) {
    (void)n_in; (void)out_size;
    const float* x  = (const float*)d_in[0];
    const float* W  = (const float*)d_in[1];
    const float* b  = (const float*)d_in[2];
    // d_in[3] = level (scalar, always 0) — ignored
    const int*   ei = (const int*)d_in[4];
    const float* ew = (const float*)d_in[5];

    int n = in_sizes[0] / FD;
    int e = in_sizes[4] / 2;
    const int* src = ei;
    const int* dst = ei + e;

    if (g_s2 == nullptr) {
        cudaStreamCreateWithFlags(&g_s2, cudaStreamNonBlocking);
        cudaEventCreateWithFlags(&g_evFork, cudaEventDisableTiming);
        cudaEventCreateWithFlags(&g_evJoin, cudaEventDisableTiming);
    }

    // fork: GEMM runs on g_s2 concurrently with the edge/CSR pipeline
    cudaEventRecord(g_evFork, 0);
    cudaStreamWaitEvent(g_s2, g_evFork, 0);
    k_gemm<<<(n + BM - 1) / BM, 256, 0, g_s2>>>(x, W, n);
    cudaEventRecord(g_evJoin, g_s2);

    // edge / CSR pipeline on the default stream (g_acc/g_total/g_done zero by invariant)
    int e4 = (e + 1023) / 1024;          // blocks of 256 threads x 4 edges
    k_deg  <<<e4, 256>>>(dst, ew, e);

    int nb = (n + 1023) / 1024;
    k_scan <<<nb, 1024>>>(n, nb);

    k_place<<<e4, 256>>>(src, dst, ew, e);

    // join: gather needs both h and the CSR
    cudaStreamWaitEvent(0, g_evJoin, 0);
    k_gather<<<(n * 32 + 255) / 256, 256>>>(b, (float*)d_out, n);
}